// round 17
// baseline (speedup 1.0000x reference)
#include <cuda_runtime.h>
#include <cstdint>

// ComparatorNBit: A,B float32 [N,32] in {0,1}, MSB first.
// Exact Boolean algebra => 32-bit unsigned compare of packed words.
//   d_out[0..N) = a_gt_b,  d_out[N..2N) = a_eq_b
//
// TERMINAL KERNEL (plateau at ~6.93 TB/s = measured chip ceiling for this
// streaming mix; kernel runs within 0.4% of 528MB/6.93TB/s floor):
//  - flat grid, block=128, __launch_bounds__(128,9): 56 regs -> 9 CTAs/SM,
//    36 warps resident
//  - 8 lanes per row chunk, 6 adjacent rows per group: 12 front-batched
//    LDG.128/thread in a 768B span; warp reads contiguous 3KB per array
//  - nibble value via 3 FFMA (exact on {0,1} floats); cross-lane MSB-first
//    priority via ballot + lsb isolate
//  - stores split across lanes 0 (gt) and 1 (eq), 3x float2 each

#define RPG 6

__device__ __forceinline__ float nibf(const float4& v) {
    return fmaf(v.x, 8.0f, fmaf(v.y, 4.0f, fmaf(v.z, 2.0f, v.w)));
}

__global__ void __launch_bounds__(128, 9) comparator_nbit_kernel(
    const float4* __restrict__ A4,
    const float4* __restrict__ B4,
    float* __restrict__ out,
    int n)
{
    int gid = blockIdx.x * blockDim.x + threadIdx.x;
    int g   = gid >> 3;                 // group: rows 6g .. 6g+5
    int sub = gid & 7;                  // 16B chunk within a row (0 = MSBs)
    int r0  = g * RPG;
    if (r0 >= n) return;

    float4 a[RPG], b[RPG];
    if (r0 + RPG - 1 < n) {
        size_t base = (size_t)r0 * 8 + sub;
        #pragma unroll
        for (int i = 0; i < RPG; i++) {
            a[i] = A4[base + 8 * i];
            b[i] = B4[base + 8 * i];
        }
    } else {
        #pragma unroll
        for (int i = 0; i < RPG; i++) {   // tail: clamp, extras discarded
            int r = min(r0 + i, n - 1);
            size_t idx = (size_t)r * 8 + sub;
            a[i] = A4[idx];
            b[i] = B4[idx];
        }
    }

    unsigned bal_ne[RPG], bal_gt[RPG];
    #pragma unroll
    for (int i = 0; i < RPG; i++) {
        float fa = nibf(a[i]);
        float fb = nibf(b[i]);
        bal_ne[i] = __ballot_sync(0xffffffffu, fa != fb);
        bal_gt[i] = __ballot_sync(0xffffffffu, fa >  fb);
    }

    if (sub < 2) {
        unsigned shift = threadIdx.x & 24u;   // this group's byte of the ballot
        float v[RPG];
        if (sub == 0) {                        // lane 0: a_gt_b
            #pragma unroll
            for (int i = 0; i < RPG; i++) {
                unsigned ne8 = (bal_ne[i] >> shift) & 0xFFu;
                unsigned lsb = ne8 & (0u - ne8);   // first differing nibble
                v[i] = ((bal_gt[i] >> shift) & lsb) ? 1.0f : 0.0f;
            }
            if (r0 + RPG - 1 < n) {            // r0 = 6g even -> float2 aligned
                #pragma unroll
                for (int i = 0; i < RPG; i += 2)
                    *(float2*)(out + r0 + i) = make_float2(v[i], v[i + 1]);
            } else {
                #pragma unroll
                for (int i = 0; i < RPG; i++)
                    if (r0 + i < n) out[r0 + i] = v[i];
            }
        } else {                               // lane 1: a_eq_b
            #pragma unroll
            for (int i = 0; i < RPG; i++) {
                unsigned ne8 = (bal_ne[i] >> shift) & 0xFFu;
                v[i] = (ne8 == 0u) ? 1.0f : 0.0f;
            }
            if (r0 + RPG - 1 < n) {
                #pragma unroll
                for (int i = 0; i < RPG; i += 2)
                    *(float2*)(out + n + r0 + i) = make_float2(v[i], v[i + 1]);
            } else {
                #pragma unroll
                for (int i = 0; i < RPG; i++)
                    if (r0 + i < n) out[n + r0 + i] = v[i];
            }
        }
    }
}

extern "C" void kernel_launch(void* const* d_in, const int* in_sizes, int n_in,
                              void* d_out, int out_size)
{
    const float4* A4 = (const float4*)d_in[0];
    const float4* B4 = (const float4*)d_in[1];
    float* out = (float*)d_out;

    int n = in_sizes[0] / 32;                            // rows
    long long groups = (n + RPG - 1) / RPG;
    long long total_threads = groups * 8;
    int block = 128;
    int grid = (int)((total_threads + block - 1) / block);

    comparator_nbit_kernel<<<grid, block>>>(A4, B4, out, n);
}